// round 1
// baseline (speedup 1.0000x reference)
#include <cuda_runtime.h>
#include <cuda_bf16.h>
#include <cstdint>

// Problem constants
#define BATCH 256
#define SEQ   256
#define EMBD  512
#define HEAD  64
#define MROWS (BATCH * SEQ)   // 65536

// Scratch for projected q, k, v (device globals: no allocation allowed)
__device__ float g_q[(size_t)MROWS * HEAD];
__device__ float g_k[(size_t)MROWS * HEAD];
__device__ float g_v[(size_t)MROWS * HEAD];

// ---------------------------------------------------------------------------
// QKV projection: C = x @ W + b for each of {q,k,v} selected by blockIdx.y.
// M=65536, K=512, N=64. Block computes 64 rows x 64 cols, BK=16.
// 256 threads, each owns a 4x4 microtile. A tile stored k-major (transposed)
// with row stride 68 floats so float4 reads stay 16B-aligned and conflict-free.
// ---------------------------------------------------------------------------
__global__ __launch_bounds__(256) void qkv_gemm(
    const float* __restrict__ x,
    const float* __restrict__ Wq, const float* __restrict__ bq,
    const float* __restrict__ Wk, const float* __restrict__ bk,
    const float* __restrict__ Wv, const float* __restrict__ bv)
{
    const float* W;
    const float* bias;
    float* out;
    if (blockIdx.y == 0)      { W = Wq; bias = bq; out = g_q; }
    else if (blockIdx.y == 1) { W = Wk; bias = bk; out = g_k; }
    else                      { W = Wv; bias = bv; out = g_v; }

    __shared__ float Ast[16 * 68];  // [k][row], row-major over 64 rows (+4 pad)
    __shared__ float Bs [16 * 68];  // [k][col]

    const int tid = threadIdx.x;
    const int tx  = tid & 15;   // col group
    const int ty  = tid >> 4;   // row group
    const int row0 = blockIdx.x * 64;

    float acc[4][4] = {};

    for (int k0 = 0; k0 < EMBD; k0 += 16) {
        // Load A tile (64 rows x 16 k), store transposed into Ast[k][row].
        {
            const int idx = tid * 4;          // 0..1023
            const int row = idx >> 4;         // 0..63
            const int kc  = idx & 15;         // 0,4,8,12
            float4 a = *(const float4*)(x + (size_t)(row0 + row) * EMBD + k0 + kc);
            Ast[(kc + 0) * 68 + row] = a.x;
            Ast[(kc + 1) * 68 + row] = a.y;
            Ast[(kc + 2) * 68 + row] = a.z;
            Ast[(kc + 3) * 68 + row] = a.w;
        }
        // Load B tile (16 k x 64 cols).
        {
            const int idx = tid * 4;          // 0..1023
            const int kc  = idx >> 6;         // 0..15
            const int col = idx & 63;         // multiple of 4
            float4 b4 = *(const float4*)(W + (size_t)(k0 + kc) * HEAD + col);
            *(float4*)(Bs + kc * 68 + col) = b4;
        }
        __syncthreads();

        #pragma unroll
        for (int kk = 0; kk < 16; kk++) {
            float4 a4 = *(const float4*)(Ast + kk * 68 + ty * 4);
            float4 b4 = *(const float4*)(Bs  + kk * 68 + tx * 4);
            float a[4] = {a4.x, a4.y, a4.z, a4.w};
            float b[4] = {b4.x, b4.y, b4.z, b4.w};
            #pragma unroll
            for (int i = 0; i < 4; i++)
                #pragma unroll
                for (int j = 0; j < 4; j++)
                    acc[i][j] += a[i] * b[j];
        }
        __syncthreads();
    }

    float4 bb = *(const float4*)(bias + tx * 4);
    #pragma unroll
    for (int i = 0; i < 4; i++) {
        float4 o;
        o.x = acc[i][0] + bb.x;
        o.y = acc[i][1] + bb.y;
        o.z = acc[i][2] + bb.z;
        o.w = acc[i][3] + bb.w;
        *(float4*)(out + (size_t)(row0 + ty * 4 + i) * HEAD + tx * 4) = o;
    }
}

// ---------------------------------------------------------------------------
// Causal attention, flash style. One thread = one query row (q, o, scores in
// registers). Block = 128 queries of one batch. Key/value tiles of 32 rows
// staged in shared memory; all smem reads in the compute loops are
// warp-uniform (broadcast, conflict-free).
// ---------------------------------------------------------------------------
__global__ __launch_bounds__(128) void attn_kernel(float* __restrict__ out)
{
    __shared__ float4 Ks[32 * 16];  // 32 keys x 64 floats
    __shared__ float4 Vs[32 * 16];

    const int b     = blockIdx.y;
    const int t0    = blockIdx.x * 128;
    const int tid   = threadIdx.x;
    const int q_idx = t0 + tid;                 // this thread's query row
    const size_t base = (size_t)b * SEQ;

    // Load q row into registers (16 float4 = 64 floats).
    float4 q[16];
    {
        const float* qp = g_q + (base + q_idx) * HEAD;
        #pragma unroll
        for (int h = 0; h < 16; h++) q[h] = *(const float4*)(qp + h * 4);
    }

    float  m = -1e30f;
    float  l = 0.0f;
    float4 o[16];
    #pragma unroll
    for (int h = 0; h < 16; h++) o[h] = make_float4(0.f, 0.f, 0.f, 0.f);

    const int s_end = t0 + 128;                 // last key tile covers diagonal
    for (int s0 = 0; s0 < s_end; s0 += 32) {
        // Stage K and V tiles (32 x 64 floats each). i4 == srow*16 + c4.
        #pragma unroll
        for (int j = 0; j < 4; j++) {
            const int i4   = tid + j * 128;     // 0..511
            const int srow = i4 >> 4;
            const int c4   = i4 & 15;
            const size_t g = (base + s0 + srow) * HEAD + c4 * 4;
            Ks[i4] = *(const float4*)(g_k + g);
            Vs[i4] = *(const float4*)(g_v + g);
        }
        __syncthreads();

        // Scores for this tile.
        float sc[32];
        #pragma unroll
        for (int s = 0; s < 32; s++) {
            float d = 0.f;
            #pragma unroll
            for (int h = 0; h < 16; h++) {
                float4 kv = Ks[s * 16 + h];
                d += q[h].x * kv.x + q[h].y * kv.y + q[h].z * kv.z + q[h].w * kv.w;
            }
            sc[s] = (s0 + s <= q_idx) ? d * 0.125f : -1e30f;  // 1/sqrt(64)
        }

        // Online softmax update.
        float tm = sc[0];
        #pragma unroll
        for (int s = 1; s < 32; s++) tm = fmaxf(tm, sc[s]);
        const float m_new = fmaxf(m, tm);
        const float corr  = __expf(m - m_new);
        l *= corr;
        #pragma unroll
        for (int h = 0; h < 16; h++) {
            o[h].x *= corr; o[h].y *= corr; o[h].z *= corr; o[h].w *= corr;
        }
        #pragma unroll
        for (int s = 0; s < 32; s++) {
            const float p = __expf(sc[s] - m_new);
            l += p;
            #pragma unroll
            for (int h = 0; h < 16; h++) {
                float4 vv = Vs[s * 16 + h];
                o[h].x += p * vv.x; o[h].y += p * vv.y;
                o[h].z += p * vv.z; o[h].w += p * vv.w;
            }
        }
        m = m_new;
        __syncthreads();
    }

    const float inv = 1.0f / l;
    float* op = out + (base + q_idx) * HEAD;
    #pragma unroll
    for (int h = 0; h < 16; h++) {
        float4 r;
        r.x = o[h].x * inv; r.y = o[h].y * inv;
        r.z = o[h].z * inv; r.w = o[h].w * inv;
        *(float4*)(op + h * 4) = r;
    }
}

// ---------------------------------------------------------------------------
// Launch. Inputs (metadata order): x, Wk, bk, Wq, bq, Wv, bv.
// ---------------------------------------------------------------------------
extern "C" void kernel_launch(void* const* d_in, const int* in_sizes, int n_in,
                              void* d_out, int out_size)
{
    const float* x  = (const float*)d_in[0];
    const float* Wk = (const float*)d_in[1];
    const float* bk = (const float*)d_in[2];
    const float* Wq = (const float*)d_in[3];
    const float* bq = (const float*)d_in[4];
    const float* Wv = (const float*)d_in[5];
    const float* bv = (const float*)d_in[6];
    float* out = (float*)d_out;

    dim3 ggrid(MROWS / 64, 3);
    qkv_gemm<<<ggrid, 256>>>(x, Wq, bq, Wk, bk, Wv, bv);

    dim3 agrid(SEQ / 128, BATCH);
    attn_kernel<<<agrid, 128>>>(out);
}

// round 3
// speedup vs baseline: 1.7180x; 1.7180x over previous
#include <cuda_runtime.h>
#include <cuda_bf16.h>
#include <cstdint>

// Problem constants
#define BATCH 256
#define SEQ   256
#define EMBD  512
#define HEAD  64
#define MROWS (BATCH * SEQ)   // 65536

// Scratch for projected q, k, v (device globals: no allocation allowed)
__device__ float g_q[(size_t)MROWS * HEAD];
__device__ float g_k[(size_t)MROWS * HEAD];
__device__ float g_v[(size_t)MROWS * HEAD];

__device__ __forceinline__ uint32_t f2tf32(float f) {
    uint32_t r;
    asm("cvt.rn.tf32.f32 %0, %1;" : "=r"(r) : "f"(f));
    return r;
}

// m16n8k8 tf32 MMA with fp32 accumulate (HMMA, baseline sm_80+ feature).
__device__ __forceinline__ void mma_tf32(float d[4], const uint32_t a[4],
                                         const uint32_t b[2]) {
    asm volatile(
        "mma.sync.aligned.m16n8k8.row.col.f32.tf32.tf32.f32 "
        "{%0,%1,%2,%3}, {%4,%5,%6,%7}, {%8,%9}, {%0,%1,%2,%3};"
        : "+f"(d[0]), "+f"(d[1]), "+f"(d[2]), "+f"(d[3])
        : "r"(a[0]), "r"(a[1]), "r"(a[2]), "r"(a[3]), "r"(b[0]), "r"(b[1]));
}

// ---------------------------------------------------------------------------
// QKV projection with tf32 mma.sync.
// CTA: M=128 rows x N=192 cols (q|k|v), K=512 in 16 chunks of 32.
// 8 warps arranged 4(M) x 2(N); warp tile 32x96 = 2 m-tiles x 12 n-tiles.
// A staged [m][k] stride 44 (conflict-free frag loads, 16B-aligned rows);
// B staged [k][n] stride 200 (conflict-free).
// ---------------------------------------------------------------------------
#define ASTRIDE 44
#define BSTRIDE 200

__global__ __launch_bounds__(256, 1) void qkv_mma(
    const float* __restrict__ x,
    const float* __restrict__ Wq, const float* __restrict__ bq,
    const float* __restrict__ Wk, const float* __restrict__ bk,
    const float* __restrict__ Wv, const float* __restrict__ bv)
{
    __shared__ __align__(16) uint32_t sA[128 * ASTRIDE];  // 22528 B
    __shared__ __align__(16) uint32_t sB[32 * BSTRIDE];   // 25600 B

    const int tid   = threadIdx.x;
    const int wid   = tid >> 5;
    const int lane  = tid & 31;
    const int g     = lane >> 2;        // group 0..7
    const int tg    = lane & 3;         // thread-in-group 0..3
    const int warpM = (wid & 3) * 32;   // 0,32,64,96
    const int warpN = (wid >> 2) * 96;  // 0,96
    const int row0  = blockIdx.x * 128;

    const float* Ws[3] = {Wq, Wk, Wv};

    float acc[2][12][4];
    #pragma unroll
    for (int mt = 0; mt < 2; mt++)
        #pragma unroll
        for (int nt = 0; nt < 12; nt++)
            #pragma unroll
            for (int i = 0; i < 4; i++) acc[mt][nt][i] = 0.f;

    for (int c = 0; c < 16; c++) {
        const int k0 = c * 32;

        // Stage A: 128 rows x 32 k, fp32 -> tf32 (RN).
        #pragma unroll
        for (int i = 0; i < 4; i++) {
            const int idx = tid + i * 256;      // 0..1023 float4s
            const int row = idx >> 3;
            const int c4  = idx & 7;
            float4 a = *(const float4*)(x + (size_t)(row0 + row) * EMBD + k0 + c4 * 4);
            uint4 t;
            t.x = f2tf32(a.x); t.y = f2tf32(a.y); t.z = f2tf32(a.z); t.w = f2tf32(a.w);
            *(uint4*)(sA + row * ASTRIDE + c4 * 4) = t;
        }
        // Stage B: 3 weights x 32 k x 64 n -> sB[k][w*64+n].
        #pragma unroll
        for (int i = 0; i < 6; i++) {
            const int idx = tid + i * 256;      // 0..1535 float4s
            const int w   = idx >> 9;
            const int rem = idx & 511;
            const int kk  = rem >> 4;
            const int n4  = rem & 15;
            float4 b = *(const float4*)(Ws[w] + (size_t)(k0 + kk) * HEAD + n4 * 4);
            uint4 t;
            t.x = f2tf32(b.x); t.y = f2tf32(b.y); t.z = f2tf32(b.z); t.w = f2tf32(b.w);
            *(uint4*)(sB + kk * BSTRIDE + w * 64 + n4 * 4) = t;
        }
        __syncthreads();

        #pragma unroll
        for (int ks = 0; ks < 4; ks++) {
            const int kb = ks * 8;
            uint32_t af[2][4];
            #pragma unroll
            for (int mt = 0; mt < 2; mt++) {
                const int rb = warpM + mt * 16 + g;
                const uint32_t* p = sA + rb * ASTRIDE + kb + tg;
                af[mt][0] = p[0];
                af[mt][1] = p[8 * ASTRIDE];
                af[mt][2] = p[4];
                af[mt][3] = p[8 * ASTRIDE + 4];
            }
            uint32_t bf[12][2];
            #pragma unroll
            for (int nt = 0; nt < 12; nt++) {
                const int col = warpN + nt * 8 + g;
                const uint32_t* p = sB + (kb + tg) * BSTRIDE + col;
                bf[nt][0] = p[0];
                bf[nt][1] = p[4 * BSTRIDE];
            }
            #pragma unroll
            for (int mt = 0; mt < 2; mt++)
                #pragma unroll
                for (int nt = 0; nt < 12; nt++)
                    mma_tf32(acc[mt][nt], af[mt], bf[nt]);
        }
        __syncthreads();
    }

    // Epilogue: add bias, scatter to g_q/g_k/g_v.
    const float* biases[3] = {bq, bk, bv};
    float* outs[3] = {g_q, g_k, g_v};
    #pragma unroll
    for (int mt = 0; mt < 2; mt++) {
        #pragma unroll
        for (int nt = 0; nt < 12; nt++) {
            const int col = warpN + nt * 8 + tg * 2;
            const int w   = col >> 6;
            const int n   = col & 63;
            float2 bb = *(const float2*)(biases[w] + n);
            const int r = row0 + warpM + mt * 16 + g;
            float2 v0, v1;
            v0.x = acc[mt][nt][0] + bb.x; v0.y = acc[mt][nt][1] + bb.y;
            v1.x = acc[mt][nt][2] + bb.x; v1.y = acc[mt][nt][3] + bb.y;
            *(float2*)(outs[w] + (size_t)r * HEAD + n)       = v0;
            *(float2*)(outs[w] + (size_t)(r + 8) * HEAD + n) = v1;
        }
    }
}

// ---------------------------------------------------------------------------
// Causal attention, flash style (unchanged from R1).
// ---------------------------------------------------------------------------
__global__ __launch_bounds__(128) void attn_kernel(float* __restrict__ out)
{
    __shared__ float4 Ks[32 * 16];
    __shared__ float4 Vs[32 * 16];

    const int b     = blockIdx.y;
    const int t0    = blockIdx.x * 128;
    const int tid   = threadIdx.x;
    const int q_idx = t0 + tid;
    const size_t base = (size_t)b * SEQ;

    float4 q[16];
    {
        const float* qp = g_q + (base + q_idx) * HEAD;
        #pragma unroll
        for (int h = 0; h < 16; h++) q[h] = *(const float4*)(qp + h * 4);
    }

    float  m = -1e30f;
    float  l = 0.0f;
    float4 o[16];
    #pragma unroll
    for (int h = 0; h < 16; h++) o[h] = make_float4(0.f, 0.f, 0.f, 0.f);

    const int s_end = t0 + 128;
    for (int s0 = 0; s0 < s_end; s0 += 32) {
        #pragma unroll
        for (int j = 0; j < 4; j++) {
            const int i4   = tid + j * 128;
            const int srow = i4 >> 4;
            const int c4   = i4 & 15;
            const size_t gg = (base + s0 + srow) * HEAD + c4 * 4;
            Ks[i4] = *(const float4*)(g_k + gg);
            Vs[i4] = *(const float4*)(g_v + gg);
        }
        __syncthreads();

        float sc[32];
        #pragma unroll
        for (int s = 0; s < 32; s++) {
            float d = 0.f;
            #pragma unroll
            for (int h = 0; h < 16; h++) {
                float4 kv = Ks[s * 16 + h];
                d += q[h].x * kv.x + q[h].y * kv.y + q[h].z * kv.z + q[h].w * kv.w;
            }
            sc[s] = (s0 + s <= q_idx) ? d * 0.125f : -1e30f;
        }

        float tm = sc[0];
        #pragma unroll
        for (int s = 1; s < 32; s++) tm = fmaxf(tm, sc[s]);
        const float m_new = fmaxf(m, tm);
        const float corr  = __expf(m - m_new);
        l *= corr;
        #pragma unroll
        for (int h = 0; h < 16; h++) {
            o[h].x *= corr; o[h].y *= corr; o[h].z *= corr; o[h].w *= corr;
        }
        #pragma unroll
        for (int s = 0; s < 32; s++) {
            const float p = __expf(sc[s] - m_new);
            l += p;
            #pragma unroll
            for (int h = 0; h < 16; h++) {
                float4 vv = Vs[s * 16 + h];
                o[h].x += p * vv.x; o[h].y += p * vv.y;
                o[h].z += p * vv.z; o[h].w += p * vv.w;
            }
        }
        m = m_new;
        __syncthreads();
    }

    const float inv = 1.0f / l;
    float* op = out + (base + q_idx) * HEAD;
    #pragma unroll
    for (int h = 0; h < 16; h++) {
        float4 r;
        r.x = o[h].x * inv; r.y = o[h].y * inv;
        r.z = o[h].z * inv; r.w = o[h].w * inv;
        *(float4*)(op + h * 4) = r;
    }
}

// ---------------------------------------------------------------------------
// Launch. Inputs (metadata order): x, Wk, bk, Wq, bq, Wv, bv.
// ---------------------------------------------------------------------------
extern "C" void kernel_launch(void* const* d_in, const int* in_sizes, int n_in,
                              void* d_out, int out_size)
{
    const float* x  = (const float*)d_in[0];
    const float* Wk = (const float*)d_in[1];
    const float* bk = (const float*)d_in[2];
    const float* Wq = (const float*)d_in[3];
    const float* bq = (const float*)d_in[4];
    const float* Wv = (const float*)d_in[5];
    const float* bv = (const float*)d_in[6];
    float* out = (float*)d_out;

    qkv_mma<<<MROWS / 128, 256>>>(x, Wq, bq, Wk, bk, Wv, bv);

    dim3 agrid(SEQ / 128, BATCH);
    attn_kernel<<<agrid, 128>>>(out);
}

// round 4
// speedup vs baseline: 3.0166x; 1.7558x over previous
#include <cuda_runtime.h>
#include <cuda_bf16.h>
#include <cuda_fp16.h>
#include <cstdint>

// Problem constants
#define BATCH 256
#define SEQ   256
#define EMBD  512
#define HEAD  64
#define MROWS (BATCH * SEQ)   // 65536

// Scratch for projected q, k, v (device globals: no allocation allowed)
__device__ float g_q[(size_t)MROWS * HEAD];
__device__ float g_k[(size_t)MROWS * HEAD];
__device__ float g_v[(size_t)MROWS * HEAD];

__device__ __forceinline__ uint32_t f2tf32(float f) {
    uint32_t r;
    asm("cvt.rn.tf32.f32 %0, %1;" : "=r"(r) : "f"(f));
    return r;
}

// m16n8k8 tf32 MMA with fp32 accumulate.
__device__ __forceinline__ void mma_tf32(float d[4], const uint32_t a[4],
                                         const uint32_t b[2]) {
    asm volatile(
        "mma.sync.aligned.m16n8k8.row.col.f32.tf32.tf32.f32 "
        "{%0,%1,%2,%3}, {%4,%5,%6,%7}, {%8,%9}, {%0,%1,%2,%3};"
        : "+f"(d[0]), "+f"(d[1]), "+f"(d[2]), "+f"(d[3])
        : "r"(a[0]), "r"(a[1]), "r"(a[2]), "r"(a[3]), "r"(b[0]), "r"(b[1]));
}

// m16n8k16 fp16 MMA with fp32 accumulate.
__device__ __forceinline__ void mma_f16(float d[4], const uint32_t a[4],
                                        const uint32_t b[2]) {
    asm volatile(
        "mma.sync.aligned.m16n8k16.row.col.f32.f16.f16.f32 "
        "{%0,%1,%2,%3}, {%4,%5,%6,%7}, {%8,%9}, {%0,%1,%2,%3};"
        : "+f"(d[0]), "+f"(d[1]), "+f"(d[2]), "+f"(d[3])
        : "r"(a[0]), "r"(a[1]), "r"(a[2]), "r"(a[3]), "r"(b[0]), "r"(b[1]));
}

// ---------------------------------------------------------------------------
// QKV projection with tf32 mma.sync (unchanged from R3).
// ---------------------------------------------------------------------------
#define ASTRIDE 44
#define BSTRIDE 200

__global__ __launch_bounds__(256, 1) void qkv_mma(
    const float* __restrict__ x,
    const float* __restrict__ Wq, const float* __restrict__ bq,
    const float* __restrict__ Wk, const float* __restrict__ bk,
    const float* __restrict__ Wv, const float* __restrict__ bv)
{
    __shared__ __align__(16) uint32_t sA[128 * ASTRIDE];
    __shared__ __align__(16) uint32_t sB[32 * BSTRIDE];

    const int tid   = threadIdx.x;
    const int wid   = tid >> 5;
    const int lane  = tid & 31;
    const int g     = lane >> 2;
    const int tg    = lane & 3;
    const int warpM = (wid & 3) * 32;
    const int warpN = (wid >> 2) * 96;
    const int row0  = blockIdx.x * 128;

    const float* Ws[3] = {Wq, Wk, Wv};

    float acc[2][12][4];
    #pragma unroll
    for (int mt = 0; mt < 2; mt++)
        #pragma unroll
        for (int nt = 0; nt < 12; nt++)
            #pragma unroll
            for (int i = 0; i < 4; i++) acc[mt][nt][i] = 0.f;

    for (int c = 0; c < 16; c++) {
        const int k0 = c * 32;
        #pragma unroll
        for (int i = 0; i < 4; i++) {
            const int idx = tid + i * 256;
            const int row = idx >> 3;
            const int c4  = idx & 7;
            float4 a = *(const float4*)(x + (size_t)(row0 + row) * EMBD + k0 + c4 * 4);
            uint4 t;
            t.x = f2tf32(a.x); t.y = f2tf32(a.y); t.z = f2tf32(a.z); t.w = f2tf32(a.w);
            *(uint4*)(sA + row * ASTRIDE + c4 * 4) = t;
        }
        #pragma unroll
        for (int i = 0; i < 6; i++) {
            const int idx = tid + i * 256;
            const int w   = idx >> 9;
            const int rem = idx & 511;
            const int kk  = rem >> 4;
            const int n4  = rem & 15;
            float4 b = *(const float4*)(Ws[w] + (size_t)(k0 + kk) * HEAD + n4 * 4);
            uint4 t;
            t.x = f2tf32(b.x); t.y = f2tf32(b.y); t.z = f2tf32(b.z); t.w = f2tf32(b.w);
            *(uint4*)(sB + kk * BSTRIDE + w * 64 + n4 * 4) = t;
        }
        __syncthreads();

        #pragma unroll
        for (int ks = 0; ks < 4; ks++) {
            const int kb = ks * 8;
            uint32_t af[2][4];
            #pragma unroll
            for (int mt = 0; mt < 2; mt++) {
                const int rb = warpM + mt * 16 + g;
                const uint32_t* p = sA + rb * ASTRIDE + kb + tg;
                af[mt][0] = p[0];
                af[mt][1] = p[8 * ASTRIDE];
                af[mt][2] = p[4];
                af[mt][3] = p[8 * ASTRIDE + 4];
            }
            uint32_t bf[12][2];
            #pragma unroll
            for (int nt = 0; nt < 12; nt++) {
                const int col = warpN + nt * 8 + g;
                const uint32_t* p = sB + (kb + tg) * BSTRIDE + col;
                bf[nt][0] = p[0];
                bf[nt][1] = p[4 * BSTRIDE];
            }
            #pragma unroll
            for (int mt = 0; mt < 2; mt++)
                #pragma unroll
                for (int nt = 0; nt < 12; nt++)
                    mma_tf32(acc[mt][nt], af[mt], bf[nt]);
        }
        __syncthreads();
    }

    const float* biases[3] = {bq, bk, bv};
    float* outs[3] = {g_q, g_k, g_v};
    #pragma unroll
    for (int mt = 0; mt < 2; mt++) {
        #pragma unroll
        for (int nt = 0; nt < 12; nt++) {
            const int col = warpN + nt * 8 + tg * 2;
            const int w   = col >> 6;
            const int n   = col & 63;
            float2 bb = *(const float2*)(biases[w] + n);
            const int r = row0 + warpM + mt * 16 + g;
            float2 v0, v1;
            v0.x = acc[mt][nt][0] + bb.x; v0.y = acc[mt][nt][1] + bb.y;
            v1.x = acc[mt][nt][2] + bb.x; v1.y = acc[mt][nt][3] + bb.y;
            *(float2*)(outs[w] + (size_t)r * HEAD + n)       = v0;
            *(float2*)(outs[w] + (size_t)(r + 8) * HEAD + n) = v1;
        }
    }
}

// ---------------------------------------------------------------------------
// Tensor-core flash attention.
// CTA = (batch, 128 q rows). 8 warps, warp = 16 q rows. Key tiles of 64.
// S = Q K^T via tf32 m16n8k8 (Q frags register-resident; K tf32 in smem).
// Online softmax in accumulators with quad shuffles. P -> fp16 A-frags
// (acc-pair -> k16 A-frag layout identity). PV via f16 m16n8k16 with V
// staged fp16 transposed. Q staging smem reused for K/Vt tiles.
// ---------------------------------------------------------------------------
#define KSTR 68   // sK row stride (words)
#define VSTR 72   // sVt row stride (halves)

__global__ __launch_bounds__(256, 1) void attn_mma(float* __restrict__ out)
{
    __shared__ __align__(16) uint32_t sbuf[128 * 68];          // 34816 B
    uint32_t* sK  = sbuf;                                      // [64][68] tf32
    __half*   sVt = (__half*)(sbuf + 64 * KSTR);               // [64][72] fp16

    const int tid  = threadIdx.x;
    const int wid  = tid >> 5;
    const int lane = tid & 31;
    const int g    = lane >> 2;
    const int tg   = lane & 3;
    const int b    = blockIdx.y;
    const int t0   = blockIdx.x * 128;
    const size_t base = (size_t)b * SEQ;

    // Stage Q tile [128][64] as tf32 into sbuf.
    #pragma unroll
    for (int i = 0; i < 8; i++) {
        const int idx = tid + i * 256;      // 0..2047 float4
        const int row = idx >> 4;
        const int c4  = idx & 15;
        float4 a = *(const float4*)(g_q + (base + t0 + row) * HEAD + c4 * 4);
        uint4 t;
        t.x = f2tf32(a.x); t.y = f2tf32(a.y); t.z = f2tf32(a.z); t.w = f2tf32(a.w);
        *(uint4*)(sbuf + row * KSTR + c4 * 4) = t;
    }
    __syncthreads();

    // Q fragments for this warp (16 rows x 64 k), kept in registers.
    uint32_t qf[8][4];
    {
        const int r0 = wid * 16 + g;
        #pragma unroll
        for (int ks = 0; ks < 8; ks++) {
            const uint32_t* p = sbuf + r0 * KSTR + ks * 8 + tg;
            qf[ks][0] = p[0];
            qf[ks][1] = p[8 * KSTR];
            qf[ks][2] = p[4];
            qf[ks][3] = p[8 * KSTR + 4];
        }
    }
    __syncthreads();

    float o[8][4];
    #pragma unroll
    for (int nt = 0; nt < 8; nt++)
        #pragma unroll
        for (int i = 0; i < 4; i++) o[nt][i] = 0.f;

    float m0 = -1e30f, m1 = -1e30f, l0 = 0.f, l1 = 0.f;
    const int q0 = t0 + wid * 16 + g;          // global q row (row g); +8 for g+8

    for (int s0 = 0; s0 < t0 + 128; s0 += 64) {
        // Stage K tile [64][64] as tf32.
        #pragma unroll
        for (int i = 0; i < 4; i++) {
            const int idx = tid + i * 256;      // 0..1023 float4
            const int row = idx >> 4;
            const int c4  = idx & 15;
            float4 a = *(const float4*)(g_k + (base + s0 + row) * HEAD + c4 * 4);
            uint4 t;
            t.x = f2tf32(a.x); t.y = f2tf32(a.y); t.z = f2tf32(a.z); t.w = f2tf32(a.w);
            *(uint4*)(sK + row * KSTR + c4 * 4) = t;
        }
        // Stage V tile fp16 TRANSPOSED: sVt[h][key].
        #pragma unroll
        for (int i = 0; i < 4; i++) {
            const int idx = tid + i * 256;
            const int row = idx >> 4;           // key
            const int c4  = idx & 15;
            float4 a = *(const float4*)(g_v + (base + s0 + row) * HEAD + c4 * 4);
            sVt[(c4 * 4 + 0) * VSTR + row] = __float2half_rn(a.x);
            sVt[(c4 * 4 + 1) * VSTR + row] = __float2half_rn(a.y);
            sVt[(c4 * 4 + 2) * VSTR + row] = __float2half_rn(a.z);
            sVt[(c4 * 4 + 3) * VSTR + row] = __float2half_rn(a.w);
        }
        __syncthreads();

        // Warp-level causal skip: all 16 rows above this key tile.
        if (s0 <= t0 + wid * 16 + 15) {
            // S = Q K^T (8 n-tiles of 8 keys).
            float sc[8][4];
            #pragma unroll
            for (int nt = 0; nt < 8; nt++) {
                sc[nt][0] = sc[nt][1] = sc[nt][2] = sc[nt][3] = 0.f;
            }
            #pragma unroll
            for (int ks = 0; ks < 8; ks++) {
                #pragma unroll
                for (int nt = 0; nt < 8; nt++) {
                    uint32_t bf[2];
                    const uint32_t* p = sK + (nt * 8 + g) * KSTR + ks * 8 + tg;
                    bf[0] = p[0];
                    bf[1] = p[4];
                    mma_tf32(sc[nt], qf[ks], bf);
                }
            }

            // Scale + causal mask + row maxes.
            float rmax0 = -1e30f, rmax1 = -1e30f;
            #pragma unroll
            for (int nt = 0; nt < 8; nt++) {
                const int key = s0 + nt * 8 + 2 * tg;
                sc[nt][0] = (key     <= q0    ) ? sc[nt][0] * 0.125f : -1e30f;
                sc[nt][1] = (key + 1 <= q0    ) ? sc[nt][1] * 0.125f : -1e30f;
                sc[nt][2] = (key     <= q0 + 8) ? sc[nt][2] * 0.125f : -1e30f;
                sc[nt][3] = (key + 1 <= q0 + 8) ? sc[nt][3] * 0.125f : -1e30f;
                rmax0 = fmaxf(rmax0, fmaxf(sc[nt][0], sc[nt][1]));
                rmax1 = fmaxf(rmax1, fmaxf(sc[nt][2], sc[nt][3]));
            }
            rmax0 = fmaxf(rmax0, __shfl_xor_sync(0xFFFFFFFFu, rmax0, 1));
            rmax0 = fmaxf(rmax0, __shfl_xor_sync(0xFFFFFFFFu, rmax0, 2));
            rmax1 = fmaxf(rmax1, __shfl_xor_sync(0xFFFFFFFFu, rmax1, 1));
            rmax1 = fmaxf(rmax1, __shfl_xor_sync(0xFFFFFFFFu, rmax1, 2));

            const float m0n = fmaxf(m0, rmax0);
            const float m1n = fmaxf(m1, rmax1);
            const float cr0 = __expf(m0 - m0n);
            const float cr1 = __expf(m1 - m1n);
            l0 *= cr0; l1 *= cr1;
            #pragma unroll
            for (int nt = 0; nt < 8; nt++) {
                o[nt][0] *= cr0; o[nt][1] *= cr0;
                o[nt][2] *= cr1; o[nt][3] *= cr1;
            }

            // exp -> P fp16 A-fragments.
            uint32_t pa[4][4];
            #pragma unroll
            for (int nt = 0; nt < 8; nt++) {
                const float p0 = __expf(sc[nt][0] - m0n);
                const float p1 = __expf(sc[nt][1] - m0n);
                const float p2 = __expf(sc[nt][2] - m1n);
                const float p3 = __expf(sc[nt][3] - m1n);
                l0 += p0 + p1;
                l1 += p2 + p3;
                __half2 h01 = __floats2half2_rn(p0, p1);
                __half2 h23 = __floats2half2_rn(p2, p3);
                const int kv = nt >> 1;
                const int hi = (nt & 1) * 2;
                pa[kv][hi + 0] = *(uint32_t*)&h01;
                pa[kv][hi + 1] = *(uint32_t*)&h23;
            }
            m0 = m0n; m1 = m1n;

            // O += P V (fp16 m16n8k16).
            const uint32_t* sVw = (const uint32_t*)sVt;
            #pragma unroll
            for (int kv = 0; kv < 4; kv++) {
                #pragma unroll
                for (int nt = 0; nt < 8; nt++) {
                    uint32_t bf[2];
                    const uint32_t* p = sVw + (nt * 8 + g) * (VSTR / 2) + kv * 8 + tg;
                    bf[0] = p[0];
                    bf[1] = p[4];
                    mma_f16(o[nt], pa[kv], bf);
                }
            }
        }
        __syncthreads();
    }

    // Reduce l across the quad, normalize, write out.
    l0 += __shfl_xor_sync(0xFFFFFFFFu, l0, 1);
    l0 += __shfl_xor_sync(0xFFFFFFFFu, l0, 2);
    l1 += __shfl_xor_sync(0xFFFFFFFFu, l1, 1);
    l1 += __shfl_xor_sync(0xFFFFFFFFu, l1, 2);
    const float inv0 = 1.0f / l0;
    const float inv1 = 1.0f / l1;

    float* op0 = out + (base + q0) * HEAD;
    float* op1 = out + (base + q0 + 8) * HEAD;
    #pragma unroll
    for (int nt = 0; nt < 8; nt++) {
        const int col = nt * 8 + 2 * tg;
        float2 v0, v1;
        v0.x = o[nt][0] * inv0; v0.y = o[nt][1] * inv0;
        v1.x = o[nt][2] * inv1; v1.y = o[nt][3] * inv1;
        *(float2*)(op0 + col) = v0;
        *(float2*)(op1 + col) = v1;
    }
}

// ---------------------------------------------------------------------------
// Launch. Inputs (metadata order): x, Wk, bk, Wq, bq, Wv, bv.
// ---------------------------------------------------------------------------
extern "C" void kernel_launch(void* const* d_in, const int* in_sizes, int n_in,
                              void* d_out, int out_size)
{
    const float* x  = (const float*)d_in[0];
    const float* Wk = (const float*)d_in[1];
    const float* bk = (const float*)d_in[2];
    const float* Wq = (const float*)d_in[3];
    const float* bq = (const float*)d_in[4];
    const float* Wv = (const float*)d_in[5];
    const float* bv = (const float*)d_in[6];
    float* out = (float*)d_out;

    qkv_mma<<<MROWS / 128, 256>>>(x, Wq, bq, Wk, bk, Wv, bv);

    dim3 agrid(SEQ / 128, BATCH);
    attn_mma<<<agrid, 256>>>(out);
}

// round 8
// speedup vs baseline: 3.6131x; 1.1977x over previous
#include <cuda_runtime.h>
#include <cuda_bf16.h>
#include <cuda_fp16.h>
#include <cstdint>

// Problem constants
#define BATCH 256
#define SEQ   256
#define EMBD  512
#define HEAD  64
#define MROWS (BATCH * SEQ)   // 65536

// Scratch for projected q, k, v (device globals: no allocation allowed)
__device__ float g_q[(size_t)MROWS * HEAD];
__device__ float g_k[(size_t)MROWS * HEAD];
__device__ float g_v[(size_t)MROWS * HEAD];

__device__ __forceinline__ uint32_t f2tf32(float f) {
    uint32_t r;
    asm("cvt.rn.tf32.f32 %0, %1;" : "=r"(r) : "f"(f));
    return r;
}

// m16n8k8 tf32 MMA with fp32 accumulate.
__device__ __forceinline__ void mma_tf32(float d[4], const uint32_t a[4],
                                         const uint32_t b[2]) {
    asm volatile(
        "mma.sync.aligned.m16n8k8.row.col.f32.tf32.tf32.f32 "
        "{%0,%1,%2,%3}, {%4,%5,%6,%7}, {%8,%9}, {%0,%1,%2,%3};"
        : "+f"(d[0]), "+f"(d[1]), "+f"(d[2]), "+f"(d[3])
        : "r"(a[0]), "r"(a[1]), "r"(a[2]), "r"(a[3]), "r"(b[0]), "r"(b[1]));
}

// m16n8k16 fp16 MMA with fp32 accumulate.
__device__ __forceinline__ void mma_f16(float d[4], const uint32_t a[4],
                                        const uint32_t b[2]) {
    asm volatile(
        "mma.sync.aligned.m16n8k16.row.col.f32.f16.f16.f32 "
        "{%0,%1,%2,%3}, {%4,%5,%6,%7}, {%8,%9}, {%0,%1,%2,%3};"
        : "+f"(d[0]), "+f"(d[1]), "+f"(d[2]), "+f"(d[3])
        : "r"(a[0]), "r"(a[1]), "r"(a[2]), "r"(a[3]), "r"(b[0]), "r"(b[1]));
}

__device__ __forceinline__ void cp_async16(void* smem_dst, const void* gmem_src) {
    uint32_t d = (uint32_t)__cvta_generic_to_shared(smem_dst);
    asm volatile("cp.async.cg.shared.global [%0], [%1], 16;"
                 :: "r"(d), "l"(gmem_src) : "memory");
}

// ---------------------------------------------------------------------------
// QKV projection, software-pipelined with cp.async double buffering.
// CTA: M=128 rows x N=192 cols (q|k|v), K=512 in 32 chunks of 16.
// Raw fp32 staged in smem; fp32->tf32 (RN) at fragment-load time.
// A stride 20 words, B stride 200 words: conflict-free fragment LDS,
// 16B-aligned rows for cp.async.
// ---------------------------------------------------------------------------
#define QAS 20
#define QBS 200
#define NCHUNK 32

__global__ __launch_bounds__(256, 1) void qkv_pipe(
    const float* __restrict__ x,
    const float* __restrict__ Wq, const float* __restrict__ bq,
    const float* __restrict__ Wk, const float* __restrict__ bk,
    const float* __restrict__ Wv, const float* __restrict__ bv)
{
    __shared__ __align__(16) float sA[2][128 * QAS];   // 2 x 10240 B
    __shared__ __align__(16) float sB[2][16 * QBS];    // 2 x 12800 B

    const int tid   = threadIdx.x;
    const int wid   = tid >> 5;
    const int lane  = tid & 31;
    const int g     = lane >> 2;
    const int tg    = lane & 3;
    const int warpM = (wid & 3) * 32;
    const int warpN = (wid >> 2) * 96;
    const int row0  = blockIdx.x * 128;

    const float* Ws[3] = {Wq, Wk, Wv};

    // Issue async loads for chunk c into buffer bufi.
    auto issue = [&](int c, int bufi) {
        const int k0 = c * 16;
        // A: 128 rows x 16 k = 512 x 16B segments; 2 per thread.
        #pragma unroll
        for (int i = 0; i < 2; i++) {
            const int idx = tid + i * 256;      // 0..511
            const int row = idx >> 2;
            const int seg = idx & 3;
            cp_async16(&sA[bufi][row * QAS + seg * 4],
                       x + (size_t)(row0 + row) * EMBD + k0 + seg * 4);
        }
        // B: 3 w x 16 k x 64 n = 768 x 16B segments; 3 per thread.
        #pragma unroll
        for (int i = 0; i < 3; i++) {
            const int idx = tid + i * 256;      // 0..767
            const int w   = idx >> 8;
            const int kk  = (idx >> 4) & 15;
            const int n4  = idx & 15;
            cp_async16(&sB[bufi][kk * QBS + w * 64 + n4 * 4],
                       Ws[w] + (size_t)(k0 + kk) * HEAD + n4 * 4);
        }
        asm volatile("cp.async.commit_group;" ::: "memory");
    };

    float acc[2][12][4];
    #pragma unroll
    for (int mt = 0; mt < 2; mt++)
        #pragma unroll
        for (int nt = 0; nt < 12; nt++)
            #pragma unroll
            for (int i = 0; i < 4; i++) acc[mt][nt][i] = 0.f;

    issue(0, 0);
    issue(1, 1);

    for (int c = 0; c < NCHUNK; c++) {
        asm volatile("cp.async.wait_group 1;" ::: "memory");
        __syncthreads();

        const float* A = sA[c & 1];
        const float* B = sB[c & 1];

        #pragma unroll
        for (int ks = 0; ks < 2; ks++) {
            const int kb = ks * 8;
            uint32_t af[2][4];
            #pragma unroll
            for (int mt = 0; mt < 2; mt++) {
                const float* p = A + (warpM + mt * 16 + g) * QAS + kb + tg;
                af[mt][0] = f2tf32(p[0]);
                af[mt][1] = f2tf32(p[8 * QAS]);
                af[mt][2] = f2tf32(p[4]);
                af[mt][3] = f2tf32(p[8 * QAS + 4]);
            }
            uint32_t bf[12][2];
            #pragma unroll
            for (int nt = 0; nt < 12; nt++) {
                const float* p = B + (kb + tg) * QBS + warpN + nt * 8 + g;
                bf[nt][0] = f2tf32(p[0]);
                bf[nt][1] = f2tf32(p[4 * QBS]);
            }
            #pragma unroll
            for (int mt = 0; mt < 2; mt++)
                #pragma unroll
                for (int nt = 0; nt < 12; nt++)
                    mma_tf32(acc[mt][nt], af[mt], bf[nt]);
        }
        __syncthreads();

        if (c + 2 < NCHUNK) issue(c + 2, c & 1);
        else asm volatile("cp.async.commit_group;" ::: "memory");  // keep accounting
    }

    // Epilogue: add bias, scatter to g_q/g_k/g_v.
    const float* biases[3] = {bq, bk, bv};
    float* outs[3] = {g_q, g_k, g_v};
    #pragma unroll
    for (int mt = 0; mt < 2; mt++) {
        #pragma unroll
        for (int nt = 0; nt < 12; nt++) {
            const int col = warpN + nt * 8 + tg * 2;
            const int w   = col >> 6;
            const int n   = col & 63;
            float2 bb = *(const float2*)(biases[w] + n);
            const int r = row0 + warpM + mt * 16 + g;
            float2 v0, v1;
            v0.x = acc[mt][nt][0] + bb.x; v0.y = acc[mt][nt][1] + bb.y;
            v1.x = acc[mt][nt][2] + bb.x; v1.y = acc[mt][nt][3] + bb.y;
            *(float2*)(outs[w] + (size_t)r * HEAD + n)       = v0;
            *(float2*)(outs[w] + (size_t)(r + 8) * HEAD + n) = v1;
        }
    }
}

// ---------------------------------------------------------------------------
// Tensor-core flash attention (unchanged from R4; 41.7us).
// ---------------------------------------------------------------------------
#define KSTR 68   // sK row stride (words)
#define VSTR 72   // sVt row stride (halves)

__global__ __launch_bounds__(256, 1) void attn_mma(float* __restrict__ out)
{
    __shared__ __align__(16) uint32_t sbuf[128 * 68];          // 34816 B
    uint32_t* sK  = sbuf;                                      // [64][68] tf32
    __half*   sVt = (__half*)(sbuf + 64 * KSTR);               // [64][72] fp16

    const int tid  = threadIdx.x;
    const int wid  = tid >> 5;
    const int lane = tid & 31;
    const int g    = lane >> 2;
    const int tg   = lane & 3;
    const int b    = blockIdx.y;
    const int t0   = blockIdx.x * 128;
    const size_t base = (size_t)b * SEQ;

    // Stage Q tile [128][64] as tf32 into sbuf.
    #pragma unroll
    for (int i = 0; i < 8; i++) {
        const int idx = tid + i * 256;      // 0..2047 float4
        const int row = idx >> 4;
        const int c4  = idx & 15;
        float4 a = *(const float4*)(g_q + (base + t0 + row) * HEAD + c4 * 4);
        uint4 t;
        t.x = f2tf32(a.x); t.y = f2tf32(a.y); t.z = f2tf32(a.z); t.w = f2tf32(a.w);
        *(uint4*)(sbuf + row * KSTR + c4 * 4) = t;
    }
    __syncthreads();

    // Q fragments for this warp (16 rows x 64 k), kept in registers.
    uint32_t qf[8][4];
    {
        const int r0 = wid * 16 + g;
        #pragma unroll
        for (int ks = 0; ks < 8; ks++) {
            const uint32_t* p = sbuf + r0 * KSTR + ks * 8 + tg;
            qf[ks][0] = p[0];
            qf[ks][1] = p[8 * KSTR];
            qf[ks][2] = p[4];
            qf[ks][3] = p[8 * KSTR + 4];
        }
    }
    __syncthreads();

    float o[8][4];
    #pragma unroll
    for (int nt = 0; nt < 8; nt++)
        #pragma unroll
        for (int i = 0; i < 4; i++) o[nt][i] = 0.f;

    float m0 = -1e30f, m1 = -1e30f, l0 = 0.f, l1 = 0.f;
    const int q0 = t0 + wid * 16 + g;

    for (int s0 = 0; s0 < t0 + 128; s0 += 64) {
        // Stage K tile [64][64] as tf32.
        #pragma unroll
        for (int i = 0; i < 4; i++) {
            const int idx = tid + i * 256;
            const int row = idx >> 4;
            const int c4  = idx & 15;
            float4 a = *(const float4*)(g_k + (base + s0 + row) * HEAD + c4 * 4);
            uint4 t;
            t.x = f2tf32(a.x); t.y = f2tf32(a.y); t.z = f2tf32(a.z); t.w = f2tf32(a.w);
            *(uint4*)(sK + row * KSTR + c4 * 4) = t;
        }
        // Stage V tile fp16 TRANSPOSED: sVt[h][key].
        #pragma unroll
        for (int i = 0; i < 4; i++) {
            const int idx = tid + i * 256;
            const int row = idx >> 4;
            const int c4  = idx & 15;
            float4 a = *(const float4*)(g_v + (base + s0 + row) * HEAD + c4 * 4);
            sVt[(c4 * 4 + 0) * VSTR + row] = __float2half_rn(a.x);
            sVt[(c4 * 4 + 1) * VSTR + row] = __float2half_rn(a.y);
            sVt[(c4 * 4 + 2) * VSTR + row] = __float2half_rn(a.z);
            sVt[(c4 * 4 + 3) * VSTR + row] = __float2half_rn(a.w);
        }
        __syncthreads();

        if (s0 <= t0 + wid * 16 + 15) {
            float sc[8][4];
            #pragma unroll
            for (int nt = 0; nt < 8; nt++) {
                sc[nt][0] = sc[nt][1] = sc[nt][2] = sc[nt][3] = 0.f;
            }
            #pragma unroll
            for (int ks = 0; ks < 8; ks++) {
                #pragma unroll
                for (int nt = 0; nt < 8; nt++) {
                    uint32_t bf[2];
                    const uint32_t* p = sK + (nt * 8 + g) * KSTR + ks * 8 + tg;
                    bf[0] = p[0];
                    bf[1] = p[4];
                    mma_tf32(sc[nt], qf[ks], bf);
                }
            }

            float rmax0 = -1e30f, rmax1 = -1e30f;
            #pragma unroll
            for (int nt = 0; nt < 8; nt++) {
                const int key = s0 + nt * 8 + 2 * tg;
                sc[nt][0] = (key     <= q0    ) ? sc[nt][0] * 0.125f : -1e30f;
                sc[nt][1] = (key + 1 <= q0    ) ? sc[nt][1] * 0.125f : -1e30f;
                sc[nt][2] = (key     <= q0 + 8) ? sc[nt][2] * 0.125f : -1e30f;
                sc[nt][3] = (key + 1 <= q0 + 8) ? sc[nt][3] * 0.125f : -1e30f;
                rmax0 = fmaxf(rmax0, fmaxf(sc[nt][0], sc[nt][1]));
                rmax1 = fmaxf(rmax1, fmaxf(sc[nt][2], sc[nt][3]));
            }
            rmax0 = fmaxf(rmax0, __shfl_xor_sync(0xFFFFFFFFu, rmax0, 1));
            rmax0 = fmaxf(rmax0, __shfl_xor_sync(0xFFFFFFFFu, rmax0, 2));
            rmax1 = fmaxf(rmax1, __shfl_xor_sync(0xFFFFFFFFu, rmax1, 1));
            rmax1 = fmaxf(rmax1, __shfl_xor_sync(0xFFFFFFFFu, rmax1, 2));

            const float m0n = fmaxf(m0, rmax0);
            const float m1n = fmaxf(m1, rmax1);
            const float cr0 = __expf(m0 - m0n);
            const float cr1 = __expf(m1 - m1n);
            l0 *= cr0; l1 *= cr1;
            #pragma unroll
            for (int nt = 0; nt < 8; nt++) {
                o[nt][0] *= cr0; o[nt][1] *= cr0;
                o[nt][2] *= cr1; o[nt][3] *= cr1;
            }

            uint32_t pa[4][4];
            #pragma unroll
            for (int nt = 0; nt < 8; nt++) {
                const float p0 = __expf(sc[nt][0] - m0n);
                const float p1 = __expf(sc[nt][1] - m0n);
                const float p2 = __expf(sc[nt][2] - m1n);
                const float p3 = __expf(sc[nt][3] - m1n);
                l0 += p0 + p1;
                l1 += p2 + p3;
                __half2 h01 = __floats2half2_rn(p0, p1);
                __half2 h23 = __floats2half2_rn(p2, p3);
                const int kv = nt >> 1;
                const int hi = (nt & 1) * 2;
                pa[kv][hi + 0] = *(uint32_t*)&h01;
                pa[kv][hi + 1] = *(uint32_t*)&h23;
            }
            m0 = m0n; m1 = m1n;

            const uint32_t* sVw = (const uint32_t*)sVt;
            #pragma unroll
            for (int kv = 0; kv < 4; kv++) {
                #pragma unroll
                for (int nt = 0; nt < 8; nt++) {
                    uint32_t bf[2];
                    const uint32_t* p = sVw + (nt * 8 + g) * (VSTR / 2) + kv * 8 + tg;
                    bf[0] = p[0];
                    bf[1] = p[4];
                    mma_f16(o[nt], pa[kv], bf);
                }
            }
        }
        __syncthreads();
    }

    l0 += __shfl_xor_sync(0xFFFFFFFFu, l0, 1);
    l0 += __shfl_xor_sync(0xFFFFFFFFu, l0, 2);
    l1 += __shfl_xor_sync(0xFFFFFFFFu, l1, 1);
    l1 += __shfl_xor_sync(0xFFFFFFFFu, l1, 2);
    const float inv0 = 1.0f / l0;
    const float inv1 = 1.0f / l1;

    float* op0 = out + (base + q0) * HEAD;
    float* op1 = out + (base + q0 + 8) * HEAD;
    #pragma unroll
    for (int nt = 0; nt < 8; nt++) {
        const int col = nt * 8 + 2 * tg;
        float2 v0, v1;
        v0.x = o[nt][0] * inv0; v0.y = o[nt][1] * inv0;
        v1.x = o[nt][2] * inv1; v1.y = o[nt][3] * inv1;
        *(float2*)(op0 + col) = v0;
        *(float2*)(op1 + col) = v1;
    }
}

// ---------------------------------------------------------------------------
// Launch. Inputs (metadata order): x, Wk, bk, Wq, bq, Wv, bv.
// ---------------------------------------------------------------------------
extern "C" void kernel_launch(void* const* d_in, const int* in_sizes, int n_in,
                              void* d_out, int out_size)
{
    const float* x  = (const float*)d_in[0];
    const float* Wk = (const float*)d_in[1];
    const float* bk = (const float*)d_in[2];
    const float* Wq = (const float*)d_in[3];
    const float* bq = (const float*)d_in[4];
    const float* Wv = (const float*)d_in[5];
    const float* bv = (const float*)d_in[6];
    float* out = (float*)d_out;

    qkv_pipe<<<MROWS / 128, 256>>>(x, Wq, bq, Wk, bk, Wv, bv);

    dim3 agrid(SEQ / 128, BATCH);
    attn_mma<<<agrid, 256>>>(out);
}

// round 9
// speedup vs baseline: 3.6553x; 1.0117x over previous
#include <cuda_runtime.h>
#include <cuda_bf16.h>
#include <cuda_fp16.h>
#include <cstdint>

// Problem constants
#define BATCH 256
#define SEQ   256
#define EMBD  512
#define HEAD  64
#define MROWS (BATCH * SEQ)   // 65536

// Scratch for projected q, k, v (device globals: no allocation allowed)
__device__ float g_q[(size_t)MROWS * HEAD];
__device__ float g_k[(size_t)MROWS * HEAD];
__device__ float g_v[(size_t)MROWS * HEAD];

__device__ __forceinline__ uint32_t f2tf32(float f) {
    uint32_t r;
    asm("cvt.rn.tf32.f32 %0, %1;" : "=r"(r) : "f"(f));
    return r;
}

// m16n8k8 tf32 MMA with fp32 accumulate.
__device__ __forceinline__ void mma_tf32(float d[4], const uint32_t a[4],
                                         const uint32_t b[2]) {
    asm volatile(
        "mma.sync.aligned.m16n8k8.row.col.f32.tf32.tf32.f32 "
        "{%0,%1,%2,%3}, {%4,%5,%6,%7}, {%8,%9}, {%0,%1,%2,%3};"
        : "+f"(d[0]), "+f"(d[1]), "+f"(d[2]), "+f"(d[3])
        : "r"(a[0]), "r"(a[1]), "r"(a[2]), "r"(a[3]), "r"(b[0]), "r"(b[1]));
}

// m16n8k16 fp16 MMA with fp32 accumulate.
__device__ __forceinline__ void mma_f16(float d[4], const uint32_t a[4],
                                        const uint32_t b[2]) {
    asm volatile(
        "mma.sync.aligned.m16n8k16.row.col.f32.f16.f16.f32 "
        "{%0,%1,%2,%3}, {%4,%5,%6,%7}, {%8,%9}, {%0,%1,%2,%3};"
        : "+f"(d[0]), "+f"(d[1]), "+f"(d[2]), "+f"(d[3])
        : "r"(a[0]), "r"(a[1]), "r"(a[2]), "r"(a[3]), "r"(b[0]), "r"(b[1]));
}

__device__ __forceinline__ void cp_async16(void* smem_dst, const void* gmem_src) {
    uint32_t d = (uint32_t)__cvta_generic_to_shared(smem_dst);
    asm volatile("cp.async.cg.shared.global [%0], [%1], 16;"
                 :: "r"(d), "l"(gmem_src) : "memory");
}

// ---------------------------------------------------------------------------
// QKV projection, depth-4 cp.async pipeline (dynamic smem, 4 buffers).
// CTA: M=128 rows x N=192 cols (q|k|v), K=512 in 32 chunks of 16.
// Prologue issues chunks 0..2; per chunk: wait_group<=2, ONE syncthreads,
// issue chunk c+3 (into buffer (c-1)&3, proven drained by the barrier),
// then compute chunk c. Prefetch distance = 3 chunk bodies > DRAM latency.
// Raw fp32 staged; fp32->tf32 (RN) at fragment-load time.
// ---------------------------------------------------------------------------
#define QAS 20
#define QBS 200
#define NCHUNK 32
#define ABUF (128 * QAS)          // 2560 floats per A stage
#define BBUF (16 * QBS)           // 3200 floats per B stage
#define QKV_SMEM ((4 * ABUF + 4 * BBUF) * 4)   // 92160 bytes

__global__ __launch_bounds__(256, 1) void qkv_pipe(
    const float* __restrict__ x,
    const float* __restrict__ Wq, const float* __restrict__ bq,
    const float* __restrict__ Wk, const float* __restrict__ bk,
    const float* __restrict__ Wv, const float* __restrict__ bv)
{
    extern __shared__ __align__(16) float smem[];
    float* sA = smem;               // [4][ABUF]
    float* sB = smem + 4 * ABUF;    // [4][BBUF]

    const int tid   = threadIdx.x;
    const int wid   = tid >> 5;
    const int lane  = tid & 31;
    const int g     = lane >> 2;
    const int tg    = lane & 3;
    const int warpM = (wid & 3) * 32;
    const int warpN = (wid >> 2) * 96;
    const int row0  = blockIdx.x * 128;

    const float* Ws[3] = {Wq, Wk, Wv};

    // Issue async loads for chunk c into stage buffer bufi.
    auto issue = [&](int c, int bufi) {
        const int k0 = c * 16;
        float* A = sA + bufi * ABUF;
        float* B = sB + bufi * BBUF;
        // A: 128 rows x 16 k = 512 x 16B segments; 2 per thread.
        #pragma unroll
        for (int i = 0; i < 2; i++) {
            const int idx = tid + i * 256;      // 0..511
            const int row = idx >> 2;
            const int seg = idx & 3;
            cp_async16(&A[row * QAS + seg * 4],
                       x + (size_t)(row0 + row) * EMBD + k0 + seg * 4);
        }
        // B: 3 w x 16 k x 64 n = 768 x 16B segments; 3 per thread.
        #pragma unroll
        for (int i = 0; i < 3; i++) {
            const int idx = tid + i * 256;      // 0..767
            const int w   = idx >> 8;
            const int kk  = (idx >> 4) & 15;
            const int n4  = idx & 15;
            cp_async16(&B[kk * QBS + w * 64 + n4 * 4],
                       Ws[w] + (size_t)(k0 + kk) * HEAD + n4 * 4);
        }
        asm volatile("cp.async.commit_group;" ::: "memory");
    };

    float acc[2][12][4];
    #pragma unroll
    for (int mt = 0; mt < 2; mt++)
        #pragma unroll
        for (int nt = 0; nt < 12; nt++)
            #pragma unroll
            for (int i = 0; i < 4; i++) acc[mt][nt][i] = 0.f;

    issue(0, 0);
    issue(1, 1);
    issue(2, 2);

    for (int c = 0; c < NCHUNK; c++) {
        asm volatile("cp.async.wait_group 2;" ::: "memory");
        __syncthreads();

        if (c + 3 < NCHUNK) issue(c + 3, (c + 3) & 3);
        else asm volatile("cp.async.commit_group;" ::: "memory");  // keep counting

        const float* A = sA + (c & 3) * ABUF;
        const float* B = sB + (c & 3) * BBUF;

        #pragma unroll
        for (int ks = 0; ks < 2; ks++) {
            const int kb = ks * 8;
            uint32_t af[2][4];
            #pragma unroll
            for (int mt = 0; mt < 2; mt++) {
                const float* p = A + (warpM + mt * 16 + g) * QAS + kb + tg;
                af[mt][0] = f2tf32(p[0]);
                af[mt][1] = f2tf32(p[8 * QAS]);
                af[mt][2] = f2tf32(p[4]);
                af[mt][3] = f2tf32(p[8 * QAS + 4]);
            }
            uint32_t bf[12][2];
            #pragma unroll
            for (int nt = 0; nt < 12; nt++) {
                const float* p = B + (kb + tg) * QBS + warpN + nt * 8 + g;
                bf[nt][0] = f2tf32(p[0]);
                bf[nt][1] = f2tf32(p[4 * QBS]);
            }
            #pragma unroll
            for (int mt = 0; mt < 2; mt++)
                #pragma unroll
                for (int nt = 0; nt < 12; nt++)
                    mma_tf32(acc[mt][nt], af[mt], bf[nt]);
        }
    }

    // Epilogue: add bias, scatter to g_q/g_k/g_v.
    const float* biases[3] = {bq, bk, bv};
    float* outs[3] = {g_q, g_k, g_v};
    #pragma unroll
    for (int mt = 0; mt < 2; mt++) {
        #pragma unroll
        for (int nt = 0; nt < 12; nt++) {
            const int col = warpN + nt * 8 + tg * 2;
            const int w   = col >> 6;
            const int n   = col & 63;
            float2 bb = *(const float2*)(biases[w] + n);
            const int r = row0 + warpM + mt * 16 + g;
            float2 v0, v1;
            v0.x = acc[mt][nt][0] + bb.x; v0.y = acc[mt][nt][1] + bb.y;
            v1.x = acc[mt][nt][2] + bb.x; v1.y = acc[mt][nt][3] + bb.y;
            *(float2*)(outs[w] + (size_t)r * HEAD + n)       = v0;
            *(float2*)(outs[w] + (size_t)(r + 8) * HEAD + n) = v1;
        }
    }
}

// ---------------------------------------------------------------------------
// Tensor-core flash attention (unchanged; 41us).
// ---------------------------------------------------------------------------
#define KSTR 68   // sK row stride (words)
#define VSTR 72   // sVt row stride (halves)

__global__ __launch_bounds__(256, 1) void attn_mma(float* __restrict__ out)
{
    __shared__ __align__(16) uint32_t sbuf[128 * 68];          // 34816 B
    uint32_t* sK  = sbuf;                                      // [64][68] tf32
    __half*   sVt = (__half*)(sbuf + 64 * KSTR);               // [64][72] fp16

    const int tid  = threadIdx.x;
    const int wid  = tid >> 5;
    const int lane = tid & 31;
    const int g    = lane >> 2;
    const int tg   = lane & 3;
    const int b    = blockIdx.y;
    const int t0   = blockIdx.x * 128;
    const size_t base = (size_t)b * SEQ;

    // Stage Q tile [128][64] as tf32 into sbuf.
    #pragma unroll
    for (int i = 0; i < 8; i++) {
        const int idx = tid + i * 256;      // 0..2047 float4
        const int row = idx >> 4;
        const int c4  = idx & 15;
        float4 a = *(const float4*)(g_q + (base + t0 + row) * HEAD + c4 * 4);
        uint4 t;
        t.x = f2tf32(a.x); t.y = f2tf32(a.y); t.z = f2tf32(a.z); t.w = f2tf32(a.w);
        *(uint4*)(sbuf + row * KSTR + c4 * 4) = t;
    }
    __syncthreads();

    // Q fragments for this warp (16 rows x 64 k), kept in registers.
    uint32_t qf[8][4];
    {
        const int r0 = wid * 16 + g;
        #pragma unroll
        for (int ks = 0; ks < 8; ks++) {
            const uint32_t* p = sbuf + r0 * KSTR + ks * 8 + tg;
            qf[ks][0] = p[0];
            qf[ks][1] = p[8 * KSTR];
            qf[ks][2] = p[4];
            qf[ks][3] = p[8 * KSTR + 4];
        }
    }
    __syncthreads();

    float o[8][4];
    #pragma unroll
    for (int nt = 0; nt < 8; nt++)
        #pragma unroll
        for (int i = 0; i < 4; i++) o[nt][i] = 0.f;

    float m0 = -1e30f, m1 = -1e30f, l0 = 0.f, l1 = 0.f;
    const int q0 = t0 + wid * 16 + g;

    for (int s0 = 0; s0 < t0 + 128; s0 += 64) {
        // Stage K tile [64][64] as tf32.
        #pragma unroll
        for (int i = 0; i < 4; i++) {
            const int idx = tid + i * 256;
            const int row = idx >> 4;
            const int c4  = idx & 15;
            float4 a = *(const float4*)(g_k + (base + s0 + row) * HEAD + c4 * 4);
            uint4 t;
            t.x = f2tf32(a.x); t.y = f2tf32(a.y); t.z = f2tf32(a.z); t.w = f2tf32(a.w);
            *(uint4*)(sK + row * KSTR + c4 * 4) = t;
        }
        // Stage V tile fp16 TRANSPOSED: sVt[h][key].
        #pragma unroll
        for (int i = 0; i < 4; i++) {
            const int idx = tid + i * 256;
            const int row = idx >> 4;
            const int c4  = idx & 15;
            float4 a = *(const float4*)(g_v + (base + s0 + row) * HEAD + c4 * 4);
            sVt[(c4 * 4 + 0) * VSTR + row] = __float2half_rn(a.x);
            sVt[(c4 * 4 + 1) * VSTR + row] = __float2half_rn(a.y);
            sVt[(c4 * 4 + 2) * VSTR + row] = __float2half_rn(a.z);
            sVt[(c4 * 4 + 3) * VSTR + row] = __float2half_rn(a.w);
        }
        __syncthreads();

        if (s0 <= t0 + wid * 16 + 15) {
            float sc[8][4];
            #pragma unroll
            for (int nt = 0; nt < 8; nt++) {
                sc[nt][0] = sc[nt][1] = sc[nt][2] = sc[nt][3] = 0.f;
            }
            #pragma unroll
            for (int ks = 0; ks < 8; ks++) {
                #pragma unroll
                for (int nt = 0; nt < 8; nt++) {
                    uint32_t bf[2];
                    const uint32_t* p = sK + (nt * 8 + g) * KSTR + ks * 8 + tg;
                    bf[0] = p[0];
                    bf[1] = p[4];
                    mma_tf32(sc[nt], qf[ks], bf);
                }
            }

            float rmax0 = -1e30f, rmax1 = -1e30f;
            #pragma unroll
            for (int nt = 0; nt < 8; nt++) {
                const int key = s0 + nt * 8 + 2 * tg;
                sc[nt][0] = (key     <= q0    ) ? sc[nt][0] * 0.125f : -1e30f;
                sc[nt][1] = (key + 1 <= q0    ) ? sc[nt][1] * 0.125f : -1e30f;
                sc[nt][2] = (key     <= q0 + 8) ? sc[nt][2] * 0.125f : -1e30f;
                sc[nt][3] = (key + 1 <= q0 + 8) ? sc[nt][3] * 0.125f : -1e30f;
                rmax0 = fmaxf(rmax0, fmaxf(sc[nt][0], sc[nt][1]));
                rmax1 = fmaxf(rmax1, fmaxf(sc[nt][2], sc[nt][3]));
            }
            rmax0 = fmaxf(rmax0, __shfl_xor_sync(0xFFFFFFFFu, rmax0, 1));
            rmax0 = fmaxf(rmax0, __shfl_xor_sync(0xFFFFFFFFu, rmax0, 2));
            rmax1 = fmaxf(rmax1, __shfl_xor_sync(0xFFFFFFFFu, rmax1, 1));
            rmax1 = fmaxf(rmax1, __shfl_xor_sync(0xFFFFFFFFu, rmax1, 2));

            const float m0n = fmaxf(m0, rmax0);
            const float m1n = fmaxf(m1, rmax1);
            const float cr0 = __expf(m0 - m0n);
            const float cr1 = __expf(m1 - m1n);
            l0 *= cr0; l1 *= cr1;
            #pragma unroll
            for (int nt = 0; nt < 8; nt++) {
                o[nt][0] *= cr0; o[nt][1] *= cr0;
                o[nt][2] *= cr1; o[nt][3] *= cr1;
            }

            uint32_t pa[4][4];
            #pragma unroll
            for (int nt = 0; nt < 8; nt++) {
                const float p0 = __expf(sc[nt][0] - m0n);
                const float p1 = __expf(sc[nt][1] - m0n);
                const float p2 = __expf(sc[nt][2] - m1n);
                const float p3 = __expf(sc[nt][3] - m1n);
                l0 += p0 + p1;
                l1 += p2 + p3;
                __half2 h01 = __floats2half2_rn(p0, p1);
                __half2 h23 = __floats2half2_rn(p2, p3);
                const int kv = nt >> 1;
                const int hi = (nt & 1) * 2;
                pa[kv][hi + 0] = *(uint32_t*)&h01;
                pa[kv][hi + 1] = *(uint32_t*)&h23;
            }
            m0 = m0n; m1 = m1n;

            const uint32_t* sVw = (const uint32_t*)sVt;
            #pragma unroll
            for (int kv = 0; kv < 4; kv++) {
                #pragma unroll
                for (int nt = 0; nt < 8; nt++) {
                    uint32_t bf[2];
                    const uint32_t* p = sVw + (nt * 8 + g) * (VSTR / 2) + kv * 8 + tg;
                    bf[0] = p[0];
                    bf[1] = p[4];
                    mma_f16(o[nt], pa[kv], bf);
                }
            }
        }
        __syncthreads();
    }

    l0 += __shfl_xor_sync(0xFFFFFFFFu, l0, 1);
    l0 += __shfl_xor_sync(0xFFFFFFFFu, l0, 2);
    l1 += __shfl_xor_sync(0xFFFFFFFFu, l1, 1);
    l1 += __shfl_xor_sync(0xFFFFFFFFu, l1, 2);
    const float inv0 = 1.0f / l0;
    const float inv1 = 1.0f / l1;

    float* op0 = out + (base + q0) * HEAD;
    float* op1 = out + (base + q0 + 8) * HEAD;
    #pragma unroll
    for (int nt = 0; nt < 8; nt++) {
        const int col = nt * 8 + 2 * tg;
        float2 v0, v1;
        v0.x = o[nt][0] * inv0; v0.y = o[nt][1] * inv0;
        v1.x = o[nt][2] * inv1; v1.y = o[nt][3] * inv1;
        *(float2*)(op0 + col) = v0;
        *(float2*)(op1 + col) = v1;
    }
}

// ---------------------------------------------------------------------------
// Launch. Inputs (metadata order): x, Wk, bk, Wq, bq, Wv, bv.
// ---------------------------------------------------------------------------
extern "C" void kernel_launch(void* const* d_in, const int* in_sizes, int n_in,
                              void* d_out, int out_size)
{
    const float* x  = (const float*)d_in[0];
    const float* Wk = (const float*)d_in[1];
    const float* bk = (const float*)d_in[2];
    const float* Wq = (const float*)d_in[3];
    const float* bq = (const float*)d_in[4];
    const float* Wv = (const float*)d_in[5];
    const float* bv = (const float*)d_in[6];
    float* out = (float*)d_out;

    cudaFuncSetAttribute(qkv_pipe, cudaFuncAttributeMaxDynamicSharedMemorySize,
                         QKV_SMEM);
    qkv_pipe<<<MROWS / 128, 256, QKV_SMEM>>>(x, Wq, bq, Wk, bk, Wv, bv);

    dim3 agrid(SEQ / 128, BATCH);
    attn_mma<<<agrid, 256>>>(out);
}

// round 11
// speedup vs baseline: 4.1490x; 1.1351x over previous
#include <cuda_runtime.h>
#include <cuda_bf16.h>
#include <cuda_fp16.h>
#include <cstdint>

// Problem constants
#define BATCH 256
#define SEQ   256
#define EMBD  512
#define HEAD  64
#define MROWS (BATCH * SEQ)   // 65536

// Scratch (device globals: no allocation allowed)
__device__ float g_q[(size_t)MROWS * HEAD];
__device__ float g_k[(size_t)MROWS * HEAD];
__device__ float g_v[(size_t)MROWS * HEAD];
__device__ __half g_wt[192 * EMBD];   // weights fp16, transposed [n=3*64][k=512]

__device__ __forceinline__ uint32_t f2tf32(float f) {
    uint32_t r;
    asm("cvt.rn.tf32.f32 %0, %1;" : "=r"(r) : "f"(f));
    return r;
}

// m16n8k8 tf32 MMA with fp32 accumulate.
__device__ __forceinline__ void mma_tf32(float d[4], const uint32_t a[4],
                                         const uint32_t b[2]) {
    asm volatile(
        "mma.sync.aligned.m16n8k8.row.col.f32.tf32.tf32.f32 "
        "{%0,%1,%2,%3}, {%4,%5,%6,%7}, {%8,%9}, {%0,%1,%2,%3};"
        : "+f"(d[0]), "+f"(d[1]), "+f"(d[2]), "+f"(d[3])
        : "r"(a[0]), "r"(a[1]), "r"(a[2]), "r"(a[3]), "r"(b[0]), "r"(b[1]));
}

// m16n8k16 fp16 MMA with fp32 accumulate.
__device__ __forceinline__ void mma_f16(float d[4], const uint32_t a[4],
                                        const uint32_t b[2]) {
    asm volatile(
        "mma.sync.aligned.m16n8k16.row.col.f32.f16.f16.f32 "
        "{%0,%1,%2,%3}, {%4,%5,%6,%7}, {%8,%9}, {%0,%1,%2,%3};"
        : "+f"(d[0]), "+f"(d[1]), "+f"(d[2]), "+f"(d[3])
        : "r"(a[0]), "r"(a[1]), "r"(a[2]), "r"(a[3]), "r"(b[0]), "r"(b[1]));
}

__device__ __forceinline__ void cp_async16(void* smem_dst, const void* gmem_src) {
    uint32_t d = (uint32_t)__cvta_generic_to_shared(smem_dst);
    asm volatile("cp.async.cg.shared.global [%0], [%1], 16;"
                 :: "r"(d), "l"(gmem_src) : "memory");
}

// ---------------------------------------------------------------------------
// Weight pre-pass: W{q,k,v}[k][64] fp32 -> g_wt[w*64+col][k] fp16 (RN).
// Grid 512 (one block per k), 192 threads (one per output row). Coalesced reads.
// ---------------------------------------------------------------------------
__global__ void wconv(const float* __restrict__ Wq, const float* __restrict__ Wk,
                      const float* __restrict__ Wv)
{
    const int k = blockIdx.x;
    const int n = threadIdx.x;          // 0..191
    const float* W = (n < 64) ? Wq : (n < 128) ? Wk : Wv;
    const int col = n & 63;
    g_wt[(size_t)n * EMBD + k] = __float2half_rn(W[(size_t)k * HEAD + col]);
}

// ---------------------------------------------------------------------------
// QKV projection, fp16 m16n8k16, depth-4 cp.async pipeline.
// CTA: M=128 x N=192 (q|k|v), K=512 in 32 chunks of 16.
// A staged fp32 (cvt to half2 at fragment load); B staged fp16 pre-transposed
// [n][k] (stride 24 halves -> LDS.32 frag loads hit all 32 banks once).
// ---------------------------------------------------------------------------
#define QAS 20                      // A row stride (floats)
#define QBSH 24                     // B row stride (halves)
#define NCHUNK 32
#define ABUF (128 * QAS)            // floats per A stage (2560)
#define BBUFH (192 * QBSH)          // halves per B stage (4608)
#define QKV_SMEM (4 * (ABUF * 4 + BBUFH * 2))   // 4 stages: 77824 bytes

__global__ __launch_bounds__(256, 1) void qkv_pipe(
    const float* __restrict__ x,
    const float* __restrict__ bq, const float* __restrict__ bk,
    const float* __restrict__ bv)
{
    extern __shared__ __align__(16) float smem[];
    float*  sA = smem;                               // [4][ABUF] fp32
    __half* sB = (__half*)(smem + 4 * ABUF);         // [4][BBUFH] fp16

    const int tid   = threadIdx.x;
    const int wid   = tid >> 5;
    const int lane  = tid & 31;
    const int g     = lane >> 2;
    const int tg    = lane & 3;
    const int warpM = (wid & 3) * 32;
    const int warpN = (wid >> 2) * 96;
    const int row0  = blockIdx.x * 128;

    // Issue async loads for chunk c into stage buffer bufi.
    auto issue = [&](int c, int bufi) {
        const int k0 = c * 16;
        float*  A = sA + bufi * ABUF;
        __half* B = sB + bufi * BBUFH;
        // A: 128 rows x 16 k fp32 = 512 x 16B segments; 2 per thread.
        #pragma unroll
        for (int i = 0; i < 2; i++) {
            const int idx = tid + i * 256;      // 0..511
            const int row = idx >> 2;
            const int seg = idx & 3;
            cp_async16(&A[row * QAS + seg * 4],
                       x + (size_t)(row0 + row) * EMBD + k0 + seg * 4);
        }
        // B: 192 rows x 16 k fp16 = 384 x 16B segments; <=2 per thread.
        #pragma unroll
        for (int i = 0; i < 2; i++) {
            const int idx = tid + i * 256;      // 0..511, guard at 384
            if (idx < 384) {
                const int row = idx >> 1;
                const int seg = idx & 1;
                cp_async16(&B[row * QBSH + seg * 8],
                           g_wt + (size_t)row * EMBD + k0 + seg * 8);
            }
        }
        asm volatile("cp.async.commit_group;" ::: "memory");
    };

    float acc[2][12][4];
    #pragma unroll
    for (int mt = 0; mt < 2; mt++)
        #pragma unroll
        for (int nt = 0; nt < 12; nt++)
            #pragma unroll
            for (int i = 0; i < 4; i++) acc[mt][nt][i] = 0.f;

    issue(0, 0);
    issue(1, 1);
    issue(2, 2);

    for (int c = 0; c < NCHUNK; c++) {
        asm volatile("cp.async.wait_group 2;" ::: "memory");
        __syncthreads();

        if (c + 3 < NCHUNK) issue(c + 3, (c + 3) & 3);
        else asm volatile("cp.async.commit_group;" ::: "memory");  // keep counting

        const float*    A  = sA + (c & 3) * ABUF;
        const uint32_t* Bw = (const uint32_t*)(sB + (c & 3) * BBUFH);

        // A fragments: fp32 -> half2 at load. khi offset = +8 floats.
        uint32_t af[2][4];
        #pragma unroll
        for (int mt = 0; mt < 2; mt++) {
            const float* p = A + (warpM + mt * 16 + g) * QAS + 2 * tg;
            float2 lo0 = *(const float2*)(p);
            float2 lo1 = *(const float2*)(p + 8 * QAS);
            float2 hi0 = *(const float2*)(p + 8);
            float2 hi1 = *(const float2*)(p + 8 * QAS + 8);
            __half2 h;
            h = __floats2half2_rn(lo0.x, lo0.y); af[mt][0] = *(uint32_t*)&h;
            h = __floats2half2_rn(lo1.x, lo1.y); af[mt][1] = *(uint32_t*)&h;
            h = __floats2half2_rn(hi0.x, hi0.y); af[mt][2] = *(uint32_t*)&h;
            h = __floats2half2_rn(hi1.x, hi1.y); af[mt][3] = *(uint32_t*)&h;
        }
        // B fragments: packed half2 straight from smem.
        uint32_t bf[12][2];
        #pragma unroll
        for (int nt = 0; nt < 12; nt++) {
            const uint32_t* p = Bw + (warpN + nt * 8 + g) * (QBSH / 2) + tg;
            bf[nt][0] = p[0];
            bf[nt][1] = p[4];
        }
        #pragma unroll
        for (int mt = 0; mt < 2; mt++)
            #pragma unroll
            for (int nt = 0; nt < 12; nt++)
                mma_f16(acc[mt][nt], af[mt], bf[nt]);
    }

    // Epilogue: add bias, scatter to g_q/g_k/g_v.
    const float* biases[3] = {bq, bk, bv};
    float* outs[3] = {g_q, g_k, g_v};
    #pragma unroll
    for (int mt = 0; mt < 2; mt++) {
        #pragma unroll
        for (int nt = 0; nt < 12; nt++) {
            const int col = warpN + nt * 8 + tg * 2;
            const int w   = col >> 6;
            const int n   = col & 63;
            float2 bb = *(const float2*)(biases[w] + n);
            const int r = row0 + warpM + mt * 16 + g;
            float2 v0, v1;
            v0.x = acc[mt][nt][0] + bb.x; v0.y = acc[mt][nt][1] + bb.y;
            v1.x = acc[mt][nt][2] + bb.x; v1.y = acc[mt][nt][3] + bb.y;
            *(float2*)(outs[w] + (size_t)r * HEAD + n)       = v0;
            *(float2*)(outs[w] + (size_t)(r + 8) * HEAD + n) = v1;
        }
    }
}

// ---------------------------------------------------------------------------
// Tensor-core flash attention (unchanged; 41us).
// ---------------------------------------------------------------------------
#define KSTR 68   // sK row stride (words)
#define VSTR 72   // sVt row stride (halves)

__global__ __launch_bounds__(256, 1) void attn_mma(float* __restrict__ out)
{
    __shared__ __align__(16) uint32_t sbuf[128 * 68];          // 34816 B
    uint32_t* sK  = sbuf;                                      // [64][68] tf32
    __half*   sVt = (__half*)(sbuf + 64 * KSTR);               // [64][72] fp16

    const int tid  = threadIdx.x;
    const int wid  = tid >> 5;
    const int lane = tid & 31;
    const int g    = lane >> 2;
    const int tg   = lane & 3;
    const int b    = blockIdx.y;
    const int t0   = blockIdx.x * 128;
    const size_t base = (size_t)b * SEQ;

    // Stage Q tile [128][64] as tf32 into sbuf.
    #pragma unroll
    for (int i = 0; i < 8; i++) {
        const int idx = tid + i * 256;      // 0..2047 float4
        const int row = idx >> 4;
        const int c4  = idx & 15;
        float4 a = *(const float4*)(g_q + (base + t0 + row) * HEAD + c4 * 4);
        uint4 t;
        t.x = f2tf32(a.x); t.y = f2tf32(a.y); t.z = f2tf32(a.z); t.w = f2tf32(a.w);
        *(uint4*)(sbuf + row * KSTR + c4 * 4) = t;
    }
    __syncthreads();

    // Q fragments for this warp (16 rows x 64 k), kept in registers.
    uint32_t qf[8][4];
    {
        const int r0 = wid * 16 + g;
        #pragma unroll
        for (int ks = 0; ks < 8; ks++) {
            const uint32_t* p = sbuf + r0 * KSTR + ks * 8 + tg;
            qf[ks][0] = p[0];
            qf[ks][1] = p[8 * KSTR];
            qf[ks][2] = p[4];
            qf[ks][3] = p[8 * KSTR + 4];
        }
    }
    __syncthreads();

    float o[8][4];
    #pragma unroll
    for (int nt = 0; nt < 8; nt++)
        #pragma unroll
        for (int i = 0; i < 4; i++) o[nt][i] = 0.f;

    float m0 = -1e30f, m1 = -1e30f, l0 = 0.f, l1 = 0.f;
    const int q0 = t0 + wid * 16 + g;

    for (int s0 = 0; s0 < t0 + 128; s0 += 64) {
        // Stage K tile [64][64] as tf32.
        #pragma unroll
        for (int i = 0; i < 4; i++) {
            const int idx = tid + i * 256;
            const int row = idx >> 4;
            const int c4  = idx & 15;
            float4 a = *(const float4*)(g_k + (base + s0 + row) * HEAD + c4 * 4);
            uint4 t;
            t.x = f2tf32(a.x); t.y = f2tf32(a.y); t.z = f2tf32(a.z); t.w = f2tf32(a.w);
            *(uint4*)(sK + row * KSTR + c4 * 4) = t;
        }
        // Stage V tile fp16 TRANSPOSED: sVt[h][key].
        #pragma unroll
        for (int i = 0; i < 4; i++) {
            const int idx = tid + i * 256;
            const int row = idx >> 4;
            const int c4  = idx & 15;
            float4 a = *(const float4*)(g_v + (base + s0 + row) * HEAD + c4 * 4);
            sVt[(c4 * 4 + 0) * VSTR + row] = __float2half_rn(a.x);
            sVt[(c4 * 4 + 1) * VSTR + row] = __float2half_rn(a.y);
            sVt[(c4 * 4 + 2) * VSTR + row] = __float2half_rn(a.z);
            sVt[(c4 * 4 + 3) * VSTR + row] = __float2half_rn(a.w);
        }
        __syncthreads();

        if (s0 <= t0 + wid * 16 + 15) {
            float sc[8][4];
            #pragma unroll
            for (int nt = 0; nt < 8; nt++) {
                sc[nt][0] = sc[nt][1] = sc[nt][2] = sc[nt][3] = 0.f;
            }
            #pragma unroll
            for (int ks = 0; ks < 8; ks++) {
                #pragma unroll
                for (int nt = 0; nt < 8; nt++) {
                    uint32_t bf[2];
                    const uint32_t* p = sK + (nt * 8 + g) * KSTR + ks * 8 + tg;
                    bf[0] = p[0];
                    bf[1] = p[4];
                    mma_tf32(sc[nt], qf[ks], bf);
                }
            }

            float rmax0 = -1e30f, rmax1 = -1e30f;
            #pragma unroll
            for (int nt = 0; nt < 8; nt++) {
                const int key = s0 + nt * 8 + 2 * tg;
                sc[nt][0] = (key     <= q0    ) ? sc[nt][0] * 0.125f : -1e30f;
                sc[nt][1] = (key + 1 <= q0    ) ? sc[nt][1] * 0.125f : -1e30f;
                sc[nt][2] = (key     <= q0 + 8) ? sc[nt][2] * 0.125f : -1e30f;
                sc[nt][3] = (key + 1 <= q0 + 8) ? sc[nt][3] * 0.125f : -1e30f;
                rmax0 = fmaxf(rmax0, fmaxf(sc[nt][0], sc[nt][1]));
                rmax1 = fmaxf(rmax1, fmaxf(sc[nt][2], sc[nt][3]));
            }
            rmax0 = fmaxf(rmax0, __shfl_xor_sync(0xFFFFFFFFu, rmax0, 1));
            rmax0 = fmaxf(rmax0, __shfl_xor_sync(0xFFFFFFFFu, rmax0, 2));
            rmax1 = fmaxf(rmax1, __shfl_xor_sync(0xFFFFFFFFu, rmax1, 1));
            rmax1 = fmaxf(rmax1, __shfl_xor_sync(0xFFFFFFFFu, rmax1, 2));

            const float m0n = fmaxf(m0, rmax0);
            const float m1n = fmaxf(m1, rmax1);
            const float cr0 = __expf(m0 - m0n);
            const float cr1 = __expf(m1 - m1n);
            l0 *= cr0; l1 *= cr1;
            #pragma unroll
            for (int nt = 0; nt < 8; nt++) {
                o[nt][0] *= cr0; o[nt][1] *= cr0;
                o[nt][2] *= cr1; o[nt][3] *= cr1;
            }

            uint32_t pa[4][4];
            #pragma unroll
            for (int nt = 0; nt < 8; nt++) {
                const float p0 = __expf(sc[nt][0] - m0n);
                const float p1 = __expf(sc[nt][1] - m0n);
                const float p2 = __expf(sc[nt][2] - m1n);
                const float p3 = __expf(sc[nt][3] - m1n);
                l0 += p0 + p1;
                l1 += p2 + p3;
                __half2 h01 = __floats2half2_rn(p0, p1);
                __half2 h23 = __floats2half2_rn(p2, p3);
                const int kv = nt >> 1;
                const int hi = (nt & 1) * 2;
                pa[kv][hi + 0] = *(uint32_t*)&h01;
                pa[kv][hi + 1] = *(uint32_t*)&h23;
            }
            m0 = m0n; m1 = m1n;

            const uint32_t* sVw = (const uint32_t*)sVt;
            #pragma unroll
            for (int kv = 0; kv < 4; kv++) {
                #pragma unroll
                for (int nt = 0; nt < 8; nt++) {
                    uint32_t bf[2];
                    const uint32_t* p = sVw + (nt * 8 + g) * (VSTR / 2) + kv * 8 + tg;
                    bf[0] = p[0];
                    bf[1] = p[4];
                    mma_f16(o[nt], pa[kv], bf);
                }
            }
        }
        __syncthreads();
    }

    l0 += __shfl_xor_sync(0xFFFFFFFFu, l0, 1);
    l0 += __shfl_xor_sync(0xFFFFFFFFu, l0, 2);
    l1 += __shfl_xor_sync(0xFFFFFFFFu, l1, 1);
    l1 += __shfl_xor_sync(0xFFFFFFFFu, l1, 2);
    const float inv0 = 1.0f / l0;
    const float inv1 = 1.0f / l1;

    float* op0 = out + (base + q0) * HEAD;
    float* op1 = out + (base + q0 + 8) * HEAD;
    #pragma unroll
    for (int nt = 0; nt < 8; nt++) {
        const int col = nt * 8 + 2 * tg;
        float2 v0, v1;
        v0.x = o[nt][0] * inv0; v0.y = o[nt][1] * inv0;
        v1.x = o[nt][2] * inv1; v1.y = o[nt][3] * inv1;
        *(float2*)(op0 + col) = v0;
        *(float2*)(op1 + col) = v1;
    }
}

// ---------------------------------------------------------------------------
// Launch. Inputs (metadata order): x, Wk, bk, Wq, bq, Wv, bv.
// ---------------------------------------------------------------------------
extern "C" void kernel_launch(void* const* d_in, const int* in_sizes, int n_in,
                              void* d_out, int out_size)
{
    const float* x  = (const float*)d_in[0];
    const float* Wk = (const float*)d_in[1];
    const float* bk = (const float*)d_in[2];
    const float* Wq = (const float*)d_in[3];
    const float* bq = (const float*)d_in[4];
    const float* Wv = (const float*)d_in[5];
    const float* bv = (const float*)d_in[6];
    float* out = (float*)d_out;

    wconv<<<EMBD, 192>>>(Wq, Wk, Wv);

    cudaFuncSetAttribute(qkv_pipe, cudaFuncAttributeMaxDynamicSharedMemorySize,
                         QKV_SMEM);
    qkv_pipe<<<MROWS / 128, 256, QKV_SMEM>>>(x, bq, bk, bv);

    dim3 agrid(SEQ / 128, BATCH);
    attn_mma<<<agrid, 256>>>(out);
}